// round 6
// baseline (speedup 1.0000x reference)
#include <cuda_runtime.h>
#include <cuda_fp16.h>
#include <cstdint>

#define B_SZ 4096
#define NI   512
#define NO   512
#define KK   (NI*8)          // 4096

// ---------------- scratch (device globals; no allocation allowed) ----------
__device__ __half g_a[(size_t)B_SZ * KK];   // 32 MB
__device__ __half g_b[(size_t)NO * KK];     //  4 MB

// ---------------- helpers ---------------------------------------------------
__device__ __forceinline__ uint32_t smem_u32(const void* p) {
    uint32_t a;
    asm("{ .reg .u64 t; cvta.to.shared.u64 t, %1; cvt.u32.u64 %0, t; }"
        : "=r"(a) : "l"(p));
    return a;
}
__device__ __forceinline__ void cp16(uint32_t dst, const void* src) {
    asm volatile("cp.async.cg.shared.global [%0], [%1], 16;"
                 :: "r"(dst), "l"(src));
}
__device__ __forceinline__ void ldsm4(uint32_t* r, uint32_t addr) {
    asm volatile("ldmatrix.sync.aligned.m8n8.x4.shared.b16 {%0,%1,%2,%3}, [%4];"
                 : "=r"(r[0]), "=r"(r[1]), "=r"(r[2]), "=r"(r[3]) : "r"(addr));
}
__device__ __forceinline__ void mma16816(float* d, const uint32_t* a,
                                         uint32_t b0, uint32_t b1) {
    asm volatile(
        "mma.sync.aligned.m16n8k16.row.col.f32.f16.f16.f32 "
        "{%0,%1,%2,%3}, {%4,%5,%6,%7}, {%8,%9}, {%0,%1,%2,%3};"
        : "+f"(d[0]), "+f"(d[1]), "+f"(d[2]), "+f"(d[3])
        : "r"(a[0]), "r"(a[1]), "r"(a[2]), "r"(a[3]), "r"(b0), "r"(b1));
}

// fast tanh: rel err ~1e-6, far below fp16 quantization (2^-11)
__device__ __forceinline__ float fast_tanh(float x) {
    float xc = fminf(fmaxf(x, -9.0f), 9.0f);
    float e  = __expf(2.0f * xc);
    return 1.0f - __fdividef(2.0f, e + 1.0f);
}

// ---------------- phase 1: jacobi expansion + coef convert ------------------
// 4 consecutive (b,i) elements per thread
__global__ __launch_bounds__(256) void jacobi_expand(const float* __restrict__ x) {
    int g = blockIdx.x * 256 + threadIdx.x;       // element group
    float4 xv = reinterpret_cast<const float4*>(x)[g];
    float xs[4] = {xv.x, xv.y, xv.z, xv.w};
    #pragma unroll
    for (int e = 0; e < 4; ++e) {
        float t = fast_tanh(xs[e]);
        float p[8];
        p[0] = 1.0f;
        p[1] = 2.0f * t;
        p[2] = 1.875f      * t * p[1] - 0.75f       * p[0];
        p[3] = 1.8666667f  * t * p[2] - 0.8f        * p[1];
        p[4] = 1.875f      * t * p[3] - 0.8333333f  * p[2];
        p[5] = 1.8857143f  * t * p[4] - 0.85714287f * p[3];
        p[6] = 1.8958334f  * t * p[5] - 0.875f      * p[4];
        p[7] = 1.9047619f  * t * p[6] - 0.8888889f  * p[5];
        __half h[8];
        #pragma unroll
        for (int d = 0; d < 8; ++d) h[d] = __float2half_rn(p[d]);
        *reinterpret_cast<uint4*>(g_a + (size_t)(g * 4 + e) * 8) =
            *reinterpret_cast<uint4*>(h);
    }
}

// 2 (j,i) pairs per thread
__global__ __launch_bounds__(256) void coef_convert(const float* __restrict__ coef) {
    int g = blockIdx.x * 256 + threadIdx.x;
    #pragma unroll
    for (int e = 0; e < 2; ++e) {
        int idx = g * 2 + e;
        float p[8];
        const float4* s = reinterpret_cast<const float4*>(coef + (size_t)idx * 8);
        *reinterpret_cast<float4*>(p)     = s[0];
        *reinterpret_cast<float4*>(p + 4) = s[1];
        __half h[8];
        #pragma unroll
        for (int d = 0; d < 8; ++d) h[d] = __float2half_rn(p[d]);
        *reinterpret_cast<uint4*>(g_b + (size_t)idx * 8) =
            *reinterpret_cast<uint4*>(h);
    }
}

// ---------------- phase 2: single-pass fp16 warp-MMA GEMM -------------------
// out[4096,512] = A[4096,4096] @ B[512,4096]^T, fp32 accumulate.
// BM=BN=128, BK=64. Stage = A(16KB) + B(16KB) = 32KB. 4 stages.
#define BKH 64
#define STAGE_BYTES 32768
#define NSTAGE 4
#define SMEM_DYN (1024 + NSTAGE * STAGE_BYTES)

// swizzled offset inside a [rows][64 fp16] tile: 128B rows, 16B chunks
__device__ __forceinline__ uint32_t swoff(int row, int chunk) {
    return (uint32_t)(row * 128 + ((chunk ^ (row & 7)) * 16));
}

// load one 128-row x 64-fp16 tile (16KB) with cp.async
__device__ __forceinline__ void load_tile(uint32_t sdst,
                                          const __half* gsrc, int tid) {
    #pragma unroll
    for (int t = 0; t < 4; ++t) {
        int idx = t * 256 + tid;           // 1024 chunks of 16B
        int row = idx >> 3, ch = idx & 7;
        cp16(sdst + swoff(row, ch),
             (const char*)(gsrc + (size_t)row * KK) + ch * 16);
    }
}

__global__ __launch_bounds__(256, 1)
void kan_gemm(float* __restrict__ out) {
    extern __shared__ char smraw[];
    uint32_t sbase = (smem_u32(smraw) + 1023) & ~1023u;

    const int tid  = threadIdx.x;
    const int lane = tid & 31;
    const int wid  = tid >> 5;
    const int wm   = wid >> 1;          // 0..3  (32-row slice)
    const int wn   = wid & 1;           // 0..1  (64-col slice)
    const int brow = blockIdx.y * 128;
    const int bcol = blockIdx.x * 128;

    const __half* A = g_a + (size_t)brow * KK;
    const __half* B = g_b + (size_t)bcol * KK;

    float acc[2][8][4];
    #pragma unroll
    for (int i = 0; i < 2; ++i)
        #pragma unroll
        for (int j = 0; j < 8; ++j)
            #pragma unroll
            for (int c = 0; c < 4; ++c) acc[i][j][c] = 0.0f;

    // ldmatrix per-lane row / chunk-half mapping
    const int ar  = lane & 15;                        // A row within m16 tile
    const int ac  = lane >> 4;                        // A k-chunk half (0/1)
    const int br0 = ((lane >> 4) << 3) + (lane & 7);  // B row within n16 pair
    const int bc  = (lane >> 3) & 1;                  // B k-chunk half (0/1)

    // prologue: stages 0..2
    #pragma unroll
    for (int t = 0; t < NSTAGE - 1; ++t) {
        uint32_t sb = sbase + t * STAGE_BYTES;
        int k0 = t * BKH;
        load_tile(sb,         A + k0, tid);
        load_tile(sb + 16384, B + k0, tid);
        asm volatile("cp.async.commit_group;" ::: "memory");
    }

    const int NIT = KK / BKH;            // 64
    for (int kt = 0; kt < NIT; ++kt) {
        asm volatile("cp.async.wait_group %0;" :: "n"(NSTAGE - 2) : "memory");
        __syncthreads();   // single barrier per iter: data ready AND slowest
                           // warp finished reading the stage we're about to
                           // overwrite (prefetch target == stage freed last iter)

        // prefetch tile kt+3 into stage (kt+3)%4
        int nk = kt + NSTAGE - 1;
        if (nk < NIT) {
            uint32_t sb = sbase + (nk % NSTAGE) * STAGE_BYTES;
            int k0 = nk * BKH;
            load_tile(sb,         A + k0, tid);
            load_tile(sb + 16384, B + k0, tid);
        }
        asm volatile("cp.async.commit_group;" ::: "memory");

        // compute from stage kt%4
        uint32_t sb = sbase + (kt % NSTAGE) * STAGE_BYTES;
        uint32_t aB = sb, bB = sb + 16384;

        #pragma unroll
        for (int s = 0; s < 4; ++s) {            // 4 k16 steps in BK=64
            uint32_t a[2][4];
            #pragma unroll
            for (int mt = 0; mt < 2; ++mt) {
                int row = wm * 32 + mt * 16 + ar;
                ldsm4(a[mt], aB + swoff(row, s * 2 + ac));
            }
            uint32_t b[4][4];
            #pragma unroll
            for (int p = 0; p < 4; ++p) {
                int row = wn * 64 + p * 16 + br0;
                ldsm4(b[p], bB + swoff(row, s * 2 + bc));
            }
            #pragma unroll
            for (int mt = 0; mt < 2; ++mt)
                #pragma unroll
                for (int p = 0; p < 4; ++p) {
                    mma16816(acc[mt][2*p],   a[mt], b[p][0], b[p][1]);
                    mma16816(acc[mt][2*p+1], a[mt], b[p][2], b[p][3]);
                }
        }
    }

    // epilogue: c-fragment layout -> float2 stores
    const int r0 = brow + wm * 32 + (lane >> 2);
    const int c0 = bcol + wn * 64 + (lane & 3) * 2;
    #pragma unroll
    for (int mt = 0; mt < 2; ++mt) {
        #pragma unroll
        for (int nt = 0; nt < 8; ++nt) {
            float* p = out + (size_t)(r0 + mt * 16) * NO + c0 + nt * 8;
            *reinterpret_cast<float2*>(p) =
                make_float2(acc[mt][nt][0], acc[mt][nt][1]);
            *reinterpret_cast<float2*>(p + 8 * NO) =
                make_float2(acc[mt][nt][2], acc[mt][nt][3]);
        }
    }
}

// ---------------- launcher ---------------------------------------------------
extern "C" void kernel_launch(void* const* d_in, const int* in_sizes, int n_in,
                              void* d_out, int out_size)
{
    const float* x    = (const float*)d_in[0];   // [4096, 512]
    const float* coef = (const float*)d_in[1];   // [512, 512, 8]
    float* out        = (float*)d_out;           // [4096, 512]

    cudaFuncSetAttribute(kan_gemm, cudaFuncAttributeMaxDynamicSharedMemorySize,
                         SMEM_DYN);

    jacobi_expand<<<(B_SZ * NI) / (256 * 4), 256>>>(x);
    coef_convert<<<(NO * NI) / (256 * 2), 256>>>(coef);

    dim3 grid(NO / 128, B_SZ / 128);             // (4, 32)
    kan_gemm<<<grid, 256, SMEM_DYN>>>(out);
}

// round 7
// speedup vs baseline: 1.0536x; 1.0536x over previous
#include <cuda_runtime.h>
#include <cuda_fp16.h>
#include <cstdint>

#define B_SZ 4096
#define NI   512
#define NO   512
#define KK   (NI*8)          // 4096

// ---------------- scratch (device globals; no allocation allowed) ----------
__device__ __half g_a[(size_t)B_SZ * KK];   // 32 MB
__device__ __half g_b[(size_t)NO * KK];     //  4 MB

// ---------------- helpers ---------------------------------------------------
__device__ __forceinline__ uint32_t smem_u32(const void* p) {
    uint32_t a;
    asm("{ .reg .u64 t; cvta.to.shared.u64 t, %1; cvt.u32.u64 %0, t; }"
        : "=r"(a) : "l"(p));
    return a;
}
__device__ __forceinline__ void cp16(uint32_t dst, const void* src) {
    asm volatile("cp.async.cg.shared.global [%0], [%1], 16;"
                 :: "r"(dst), "l"(src));
}
__device__ __forceinline__ void ldsm4(uint32_t* r, uint32_t addr) {
    asm volatile("ldmatrix.sync.aligned.m8n8.x4.shared.b16 {%0,%1,%2,%3}, [%4];"
                 : "=r"(r[0]), "=r"(r[1]), "=r"(r[2]), "=r"(r[3]) : "r"(addr));
}
__device__ __forceinline__ void mma16816(float* d, const uint32_t* a,
                                         uint32_t b0, uint32_t b1) {
    asm volatile(
        "mma.sync.aligned.m16n8k16.row.col.f32.f16.f16.f32 "
        "{%0,%1,%2,%3}, {%4,%5,%6,%7}, {%8,%9}, {%0,%1,%2,%3};"
        : "+f"(d[0]), "+f"(d[1]), "+f"(d[2]), "+f"(d[3])
        : "r"(a[0]), "r"(a[1]), "r"(a[2]), "r"(a[3]), "r"(b0), "r"(b1));
}

// fast tanh: rel err ~1e-6, far below fp16 quantization (2^-11)
__device__ __forceinline__ float fast_tanh(float x) {
    float xc = fminf(fmaxf(x, -9.0f), 9.0f);
    float e  = __expf(2.0f * xc);
    return 1.0f - __fdividef(2.0f, e + 1.0f);
}

__device__ __forceinline__ void jacobi8_to_half(float t, __half* h) {
    float p[8];
    p[0] = 1.0f;
    p[1] = 2.0f * t;
    p[2] = 1.875f      * t * p[1] - 0.75f       * p[0];
    p[3] = 1.8666667f  * t * p[2] - 0.8f        * p[1];
    p[4] = 1.875f      * t * p[3] - 0.8333333f  * p[2];
    p[5] = 1.8857143f  * t * p[4] - 0.85714287f * p[3];
    p[6] = 1.8958334f  * t * p[5] - 0.875f      * p[4];
    p[7] = 1.9047619f  * t * p[6] - 0.8888889f  * p[5];
    #pragma unroll
    for (int d = 0; d < 8; ++d) h[d] = __float2half_rn(p[d]);
}

// ---------------- phase 1: jacobi expansion + coef convert ------------------
// 2 elems/thread, STRIDED by 256 so every store wavefront stays coalesced
__global__ __launch_bounds__(256) void jacobi_expand(const float* __restrict__ x) {
    int base = blockIdx.x * 512;
    #pragma unroll
    for (int e = 0; e < 2; ++e) {
        int g = base + e * 256 + threadIdx.x;
        float t = fast_tanh(x[g]);
        __half h[8];
        jacobi8_to_half(t, h);
        *reinterpret_cast<uint4*>(g_a + (size_t)g * 8) =
            *reinterpret_cast<uint4*>(h);
    }
}

__global__ __launch_bounds__(256) void coef_convert(const float* __restrict__ coef) {
    int base = blockIdx.x * 512;
    #pragma unroll
    for (int e = 0; e < 2; ++e) {
        int idx = base + e * 256 + threadIdx.x;
        float p[8];
        const float4* s = reinterpret_cast<const float4*>(coef + (size_t)idx * 8);
        *reinterpret_cast<float4*>(p)     = s[0];
        *reinterpret_cast<float4*>(p + 4) = s[1];
        __half h[8];
        #pragma unroll
        for (int d = 0; d < 8; ++d) h[d] = __float2half_rn(p[d]);
        *reinterpret_cast<uint4*>(g_b + (size_t)idx * 8) =
            *reinterpret_cast<uint4*>(h);
    }
}

// ---------------- phase 2: single-pass fp16 warp-MMA GEMM -------------------
// out[4096,512] = A[4096,4096] @ B[512,4096]^T, fp32 accumulate.
// BM=BN=128, BK=64. Stage = A(16KB) + B(16KB) = 32KB. 4 stages.
#define BKH 64
#define STAGE_BYTES 32768
#define NSTAGE 4
#define SMEM_DYN (1024 + NSTAGE * STAGE_BYTES)

// swizzled offset inside a [rows][64 fp16] tile: 128B rows, 16B chunks
__device__ __forceinline__ uint32_t swoff(int row, int chunk) {
    return (uint32_t)(row * 128 + ((chunk ^ (row & 7)) * 16));
}

// load one 128-row x 64-fp16 tile (16KB) with cp.async
__device__ __forceinline__ void load_tile(uint32_t sdst,
                                          const __half* gsrc, int tid) {
    #pragma unroll
    for (int t = 0; t < 4; ++t) {
        int idx = t * 256 + tid;           // 1024 chunks of 16B
        int row = idx >> 3, ch = idx & 7;
        cp16(sdst + swoff(row, ch),
             (const char*)(gsrc + (size_t)row * KK) + ch * 16);
    }
}

__global__ __launch_bounds__(256, 1)
void kan_gemm(float* __restrict__ out) {
    extern __shared__ char smraw[];
    uint32_t sbase = (smem_u32(smraw) + 1023) & ~1023u;

    const int tid  = threadIdx.x;
    const int lane = tid & 31;
    const int wid  = tid >> 5;
    const int wm   = wid >> 1;          // 0..3  (32-row slice)
    const int wn   = wid & 1;           // 0..1  (64-col slice)
    const int brow = blockIdx.y * 128;
    const int bcol = blockIdx.x * 128;

    const __half* A = g_a + (size_t)brow * KK;
    const __half* B = g_b + (size_t)bcol * KK;

    float acc[2][8][4];
    #pragma unroll
    for (int i = 0; i < 2; ++i)
        #pragma unroll
        for (int j = 0; j < 8; ++j)
            #pragma unroll
            for (int c = 0; c < 4; ++c) acc[i][j][c] = 0.0f;

    // ldmatrix per-lane row / chunk-half mapping
    const int ar  = lane & 15;                        // A row within m16 tile
    const int ac  = lane >> 4;                        // A k-chunk half (0/1)
    const int br0 = ((lane >> 4) << 3) + (lane & 7);  // B row within n16 pair
    const int bc  = (lane >> 3) & 1;                  // B k-chunk half (0/1)

    // prologue: stages 0..2
    #pragma unroll
    for (int t = 0; t < NSTAGE - 1; ++t) {
        uint32_t sb = sbase + t * STAGE_BYTES;
        int k0 = t * BKH;
        load_tile(sb,         A + k0, tid);
        load_tile(sb + 16384, B + k0, tid);
        asm volatile("cp.async.commit_group;" ::: "memory");
    }

    const int NIT = KK / BKH;            // 64
    for (int kt = 0; kt < NIT; ++kt) {
        asm volatile("cp.async.wait_group %0;" :: "n"(NSTAGE - 2) : "memory");
        __syncthreads();

        // prefetch tile kt+3 into stage (kt+3)%4
        int nk = kt + NSTAGE - 1;
        if (nk < NIT) {
            uint32_t sb = sbase + (nk % NSTAGE) * STAGE_BYTES;
            int k0 = nk * BKH;
            load_tile(sb,         A + k0, tid);
            load_tile(sb + 16384, B + k0, tid);
        }
        asm volatile("cp.async.commit_group;" ::: "memory");

        // compute from stage kt%4: preload ALL fragments for BK=64 first
        // (24 LDSM.x4 in a burst -> high LDS MLP), then 64 dependency-free HMMA.
        uint32_t sb = sbase + (kt % NSTAGE) * STAGE_BYTES;
        uint32_t aB = sb, bB = sb + 16384;

        uint32_t af[4][2][4];      // [s][mt][frag]
        uint32_t bf[4][4][4];      // [s][p][frag]
        #pragma unroll
        for (int s = 0; s < 4; ++s) {
            #pragma unroll
            for (int mt = 0; mt < 2; ++mt)
                ldsm4(af[s][mt], aB + swoff(wm * 32 + mt * 16 + ar, s * 2 + ac));
            #pragma unroll
            for (int p = 0; p < 4; ++p)
                ldsm4(bf[s][p], bB + swoff(wn * 64 + p * 16 + br0, s * 2 + bc));
        }
        #pragma unroll
        for (int s = 0; s < 4; ++s)
            #pragma unroll
            for (int mt = 0; mt < 2; ++mt)
                #pragma unroll
                for (int p = 0; p < 4; ++p) {
                    mma16816(acc[mt][2*p],   af[s][mt], bf[s][p][0], bf[s][p][1]);
                    mma16816(acc[mt][2*p+1], af[s][mt], bf[s][p][2], bf[s][p][3]);
                }
        __syncthreads();
    }

    // epilogue: c-fragment layout -> float2 stores
    const int r0 = brow + wm * 32 + (lane >> 2);
    const int c0 = bcol + wn * 64 + (lane & 3) * 2;
    #pragma unroll
    for (int mt = 0; mt < 2; ++mt) {
        #pragma unroll
        for (int nt = 0; nt < 8; ++nt) {
            float* p = out + (size_t)(r0 + mt * 16) * NO + c0 + nt * 8;
            *reinterpret_cast<float2*>(p) =
                make_float2(acc[mt][nt][0], acc[mt][nt][1]);
            *reinterpret_cast<float2*>(p + 8 * NO) =
                make_float2(acc[mt][nt][2], acc[mt][nt][3]);
        }
    }
}

// ---------------- launcher ---------------------------------------------------
extern "C" void kernel_launch(void* const* d_in, const int* in_sizes, int n_in,
                              void* d_out, int out_size)
{
    const float* x    = (const float*)d_in[0];   // [4096, 512]
    const float* coef = (const float*)d_in[1];   // [512, 512, 8]
    float* out        = (float*)d_out;           // [4096, 512]

    cudaFuncSetAttribute(kan_gemm, cudaFuncAttributeMaxDynamicSharedMemorySize,
                         SMEM_DYN);

    jacobi_expand<<<(B_SZ * NI) / 512, 256>>>(x);
    coef_convert<<<(NO * NI) / 512, 256>>>(coef);

    dim3 grid(NO / 128, B_SZ / 128);             // (4, 32)
    kan_gemm<<<grid, 256, SMEM_DYN>>>(out);
}

// round 8
// speedup vs baseline: 1.1342x; 1.0764x over previous
#include <cuda_runtime.h>
#include <cuda_fp16.h>
#include <cstdint>

#define B_SZ 4096
#define NI   512
#define NO   512
#define KK   (NI*8)          // 4096

// ---------------- scratch (device globals; no allocation allowed) ----------
__device__ __half g_a[(size_t)B_SZ * KK];   // 32 MB
__device__ __half g_b[(size_t)NO * KK];     //  4 MB

// ---------------- helpers ---------------------------------------------------
__device__ __forceinline__ uint32_t smem_u32(const void* p) {
    uint32_t a;
    asm("{ .reg .u64 t; cvta.to.shared.u64 t, %1; cvt.u32.u64 %0, t; }"
        : "=r"(a) : "l"(p));
    return a;
}
__device__ __forceinline__ void cp16(uint32_t dst, const void* src) {
    asm volatile("cp.async.cg.shared.global [%0], [%1], 16;"
                 :: "r"(dst), "l"(src));
}
__device__ __forceinline__ void ldsm4(uint32_t* r, uint32_t addr) {
    asm volatile("ldmatrix.sync.aligned.m8n8.x4.shared.b16 {%0,%1,%2,%3}, [%4];"
                 : "=r"(r[0]), "=r"(r[1]), "=r"(r[2]), "=r"(r[3]) : "r"(addr));
}
__device__ __forceinline__ void mma16816(float* d, const uint32_t* a,
                                         uint32_t b0, uint32_t b1) {
    asm volatile(
        "mma.sync.aligned.m16n8k16.row.col.f32.f16.f16.f32 "
        "{%0,%1,%2,%3}, {%4,%5,%6,%7}, {%8,%9}, {%0,%1,%2,%3};"
        : "+f"(d[0]), "+f"(d[1]), "+f"(d[2]), "+f"(d[3])
        : "r"(a[0]), "r"(a[1]), "r"(a[2]), "r"(a[3]), "r"(b0), "r"(b1));
}

// fast tanh: rel err ~1e-6, far below fp16 quantization (2^-11)
__device__ __forceinline__ float fast_tanh(float x) {
    float xc = fminf(fmaxf(x, -9.0f), 9.0f);
    float e  = __expf(2.0f * xc);
    return 1.0f - __fdividef(2.0f, e + 1.0f);
}

__device__ __forceinline__ void jacobi8_to_half(float t, __half* h) {
    float p[8];
    p[0] = 1.0f;
    p[1] = 2.0f * t;
    p[2] = 1.875f      * t * p[1] - 0.75f       * p[0];
    p[3] = 1.8666667f  * t * p[2] - 0.8f        * p[1];
    p[4] = 1.875f      * t * p[3] - 0.8333333f  * p[2];
    p[5] = 1.8857143f  * t * p[4] - 0.85714287f * p[3];
    p[6] = 1.8958334f  * t * p[5] - 0.875f      * p[4];
    p[7] = 1.9047619f  * t * p[6] - 0.8888889f  * p[5];
    #pragma unroll
    for (int d = 0; d < 8; ++d) h[d] = __float2half_rn(p[d]);
}

// ---------------- phase 1: jacobi expansion + coef convert ------------------
// 4 elems/thread, stride-256 groups: coalesced loads AND stores, 4 indep chains
__global__ __launch_bounds__(256) void jacobi_expand(const float* __restrict__ x) {
    int base = blockIdx.x * 1024 + threadIdx.x;
    float t[4];
    #pragma unroll
    for (int e = 0; e < 4; ++e) t[e] = fast_tanh(x[base + e * 256]);
    #pragma unroll
    for (int e = 0; e < 4; ++e) {
        __half h[8];
        jacobi8_to_half(t[e], h);
        *reinterpret_cast<uint4*>(g_a + (size_t)(base + e * 256) * 8) =
            *reinterpret_cast<uint4*>(h);
    }
}

__global__ __launch_bounds__(256) void coef_convert(const float* __restrict__ coef) {
    int base = blockIdx.x * 1024 + threadIdx.x;
    #pragma unroll
    for (int e = 0; e < 4; ++e) {
        int idx = base + e * 256;
        float p[8];
        const float4* s = reinterpret_cast<const float4*>(coef + (size_t)idx * 8);
        *reinterpret_cast<float4*>(p)     = s[0];
        *reinterpret_cast<float4*>(p + 4) = s[1];
        __half h[8];
        #pragma unroll
        for (int d = 0; d < 8; ++d) h[d] = __float2half_rn(p[d]);
        *reinterpret_cast<uint4*>(g_b + (size_t)idx * 8) =
            *reinterpret_cast<uint4*>(h);
    }
}

// ---------------- phase 2: single-pass fp16 warp-MMA GEMM -------------------
// out[4096,512] = A[4096,4096] @ B[512,4096]^T, fp32 accumulate.
// BM=BN=128, BK=128. Stage = A(32KB) + B(32KB) = 64KB. 3 stages = 192KB.
// Each 32KB operand stage = two concatenated 16KB [128 x 64] subtiles
// (k-halves), preserving the validated 64-col swizzle layout.
#define BKH 128
#define SUB_BYTES 16384
#define STAGE_BYTES 65536
#define NSTAGE 3
#define SMEM_DYN (1024 + NSTAGE * STAGE_BYTES)

// swizzled offset inside a [rows][64 fp16] subtile: 128B rows, 16B chunks
__device__ __forceinline__ uint32_t swoff(int row, int chunk) {
    return (uint32_t)(row * 128 + ((chunk ^ (row & 7)) * 16));
}

// load one 128-row x 64-fp16 subtile (16KB) with cp.async
__device__ __forceinline__ void load_sub(uint32_t sdst,
                                         const __half* gsrc, int tid) {
    #pragma unroll
    for (int t = 0; t < 4; ++t) {
        int idx = t * 256 + tid;           // 1024 chunks of 16B
        int row = idx >> 3, ch = idx & 7;
        cp16(sdst + swoff(row, ch),
             (const char*)(gsrc + (size_t)row * KK) + ch * 16);
    }
}

__device__ __forceinline__ void load_stage(uint32_t sb, const __half* A,
                                           const __half* B, int k0, int tid) {
    load_sub(sb,                 A + k0,      tid);
    load_sub(sb + SUB_BYTES,     A + k0 + 64, tid);
    load_sub(sb + 2 * SUB_BYTES, B + k0,      tid);
    load_sub(sb + 3 * SUB_BYTES, B + k0 + 64, tid);
}

__global__ __launch_bounds__(256, 1)
void kan_gemm(float* __restrict__ out) {
    extern __shared__ char smraw[];
    uint32_t sbase = (smem_u32(smraw) + 1023) & ~1023u;

    const int tid  = threadIdx.x;
    const int lane = tid & 31;
    const int wid  = tid >> 5;
    const int wm   = wid >> 1;          // 0..3  (32-row slice)
    const int wn   = wid & 1;           // 0..1  (64-col slice)
    const int brow = blockIdx.y * 128;
    const int bcol = blockIdx.x * 128;

    const __half* A = g_a + (size_t)brow * KK;
    const __half* B = g_b + (size_t)bcol * KK;

    float acc[2][8][4];
    #pragma unroll
    for (int i = 0; i < 2; ++i)
        #pragma unroll
        for (int j = 0; j < 8; ++j)
            #pragma unroll
            for (int c = 0; c < 4; ++c) acc[i][j][c] = 0.0f;

    // ldmatrix per-lane row / chunk-half mapping
    const int ar  = lane & 15;                        // A row within m16 tile
    const int ac  = lane >> 4;                        // A k-chunk half (0/1)
    const int br0 = ((lane >> 4) << 3) + (lane & 7);  // B row within n16 pair
    const int bc  = (lane >> 3) & 1;                  // B k-chunk half (0/1)

    // prologue: stages 0,1
    #pragma unroll
    for (int t = 0; t < NSTAGE - 1; ++t) {
        load_stage(sbase + t * STAGE_BYTES, A, B, t * BKH, tid);
        asm volatile("cp.async.commit_group;" ::: "memory");
    }

    const int NIT = KK / BKH;            // 32
    for (int kt = 0; kt < NIT; ++kt) {
        asm volatile("cp.async.wait_group %0;" :: "n"(NSTAGE - 2) : "memory");
        __syncthreads();

        // prefetch tile kt+2 into stage (kt+2)%3
        int nk = kt + NSTAGE - 1;
        if (nk < NIT) {
            load_stage(sbase + (nk % NSTAGE) * STAGE_BYTES, A, B, nk * BKH, tid);
        }
        asm volatile("cp.async.commit_group;" ::: "memory");

        // compute from stage kt%3: two 64-col k-halves x 4 k16-steps
        uint32_t sb = sbase + (kt % NSTAGE) * STAGE_BYTES;
        #pragma unroll
        for (int h = 0; h < 2; ++h) {
            uint32_t aB = sb + h * SUB_BYTES;
            uint32_t bB = sb + (2 + h) * SUB_BYTES;
            #pragma unroll
            for (int s = 0; s < 4; ++s) {
                uint32_t a[2][4];
                #pragma unroll
                for (int mt = 0; mt < 2; ++mt)
                    ldsm4(a[mt], aB + swoff(wm * 32 + mt * 16 + ar, s * 2 + ac));
                uint32_t b[4][4];
                #pragma unroll
                for (int p = 0; p < 4; ++p)
                    ldsm4(b[p], bB + swoff(wn * 64 + p * 16 + br0, s * 2 + bc));
                #pragma unroll
                for (int mt = 0; mt < 2; ++mt)
                    #pragma unroll
                    for (int p = 0; p < 4; ++p) {
                        mma16816(acc[mt][2*p],   a[mt], b[p][0], b[p][1]);
                        mma16816(acc[mt][2*p+1], a[mt], b[p][2], b[p][3]);
                    }
            }
        }
        __syncthreads();
    }

    // epilogue: c-fragment layout -> float2 stores
    const int r0 = brow + wm * 32 + (lane >> 2);
    const int c0 = bcol + wn * 64 + (lane & 3) * 2;
    #pragma unroll
    for (int mt = 0; mt < 2; ++mt) {
        #pragma unroll
        for (int nt = 0; nt < 8; ++nt) {
            float* p = out + (size_t)(r0 + mt * 16) * NO + c0 + nt * 8;
            *reinterpret_cast<float2*>(p) =
                make_float2(acc[mt][nt][0], acc[mt][nt][1]);
            *reinterpret_cast<float2*>(p + 8 * NO) =
                make_float2(acc[mt][nt][2], acc[mt][nt][3]);
        }
    }
}

// ---------------- launcher ---------------------------------------------------
extern "C" void kernel_launch(void* const* d_in, const int* in_sizes, int n_in,
                              void* d_out, int out_size)
{
    const float* x    = (const float*)d_in[0];   // [4096, 512]
    const float* coef = (const float*)d_in[1];   // [512, 512, 8]
    float* out        = (float*)d_out;           // [4096, 512]

    cudaFuncSetAttribute(kan_gemm, cudaFuncAttributeMaxDynamicSharedMemorySize,
                         SMEM_DYN);

    jacobi_expand<<<(B_SZ * NI) / 1024, 256>>>(x);
    coef_convert<<<(NO * NI) / 1024, 256>>>(coef);

    dim3 grid(NO / 128, B_SZ / 128);             // (4, 32)
    kan_gemm<<<grid, 256, SMEM_DYN>>>(out);
}